// round 7
// baseline (speedup 1.0000x reference)
#include <cuda_runtime.h>
#include <cuda_bf16.h>
#include <cstdint>

#define N_CELLS 50000
#define N_GENES 2000
#define HIDDEN 128
#define E_FULL 800000
#define E_PRUNED 400000
#define K1_PAD 2048
#define NC1 64            // K chunks (BK=32) for GEMM1
#define NC2 4             // K chunks for GEMM2
#define BROW 80           // padded SMEM row stride (32 bf16 + 8 pad) bytes
#define TILE_B 10240      // 128 rows * 80 B
#define STAGE_B 40960     // Ah | Al | Bh | Bl
#define SMEM_DYN (2 * STAGE_B)

// ---------------- device scratch (allocation-free) ----------------
__device__ float g_h[(size_t)N_CELLS * HIDDEN];
__device__ float g_hB[(size_t)N_CELLS * HIDDEN];  // split-K partial
__device__ float g_hcat[(size_t)N_CELLS * 512];   // [hsF|hdF|hsP|hdP]
__device__ __align__(16) unsigned char g_bt1_hi[(size_t)NC1 * TILE_B];
__device__ __align__(16) unsigned char g_bt1_lo[(size_t)NC1 * TILE_B];
__device__ __align__(16) unsigned char g_bt2_hi[(size_t)4 * NC2 * TILE_B];
__device__ __align__(16) unsigned char g_bt2_lo[(size_t)4 * NC2 * TILE_B];
__device__ int g_cntF[N_CELLS], g_cntP[N_CELLS];
__device__ int g_offF[N_CELLS], g_offP[N_CELLS];
__device__ int g_curF[N_CELLS], g_curP[N_CELLS];
__device__ int g_totF, g_totP;
__device__ int2 g_epF[E_FULL], g_epP[E_PRUNED];   // (src, weight-bits) in CSR order

// ---------------- helpers ----------------
__device__ __forceinline__ uint32_t smem_u32(const void* p) {
    uint32_t a;
    asm("{ .reg .u64 t; cvta.to.shared.u64 t, %1; cvt.u32.u64 %0, t; }" : "=r"(a) : "l"(p));
    return a;
}
__device__ __forceinline__ void ldsm_x4(uint32_t* r, uint32_t a) {
    asm volatile("ldmatrix.sync.aligned.m8n8.x4.shared.b16 {%0,%1,%2,%3}, [%4];"
                 : "=r"(r[0]), "=r"(r[1]), "=r"(r[2]), "=r"(r[3]) : "r"(a));
}
__device__ __forceinline__ void ldsm_x2(uint32_t* r, uint32_t a) {
    asm volatile("ldmatrix.sync.aligned.m8n8.x2.shared.b16 {%0,%1}, [%2];"
                 : "=r"(r[0]), "=r"(r[1]) : "r"(a));
}
__device__ __forceinline__ void mma_bf16(float* d, const uint32_t* a, const uint32_t* b) {
    asm volatile("mma.sync.aligned.m16n8k16.row.col.f32.bf16.bf16.f32 "
                 "{%0,%1,%2,%3}, {%4,%5,%6,%7}, {%8,%9}, {%0,%1,%2,%3};"
                 : "+f"(d[0]), "+f"(d[1]), "+f"(d[2]), "+f"(d[3])
                 : "r"(a[0]), "r"(a[1]), "r"(a[2]), "r"(a[3]), "r"(b[0]), "r"(b[1]));
}

// ---------------- setup: zero counters + pack B1 + pack B2 ----------------
#define SETUP_B1 (128 * K1_PAD)              // 262144
#define SETUP_B2 (512 * 128)                 // 65536
#define SETUP_TOTAL (SETUP_B1 + SETUP_B2 + N_CELLS)
__global__ void setup(const float* __restrict__ w1,
                      const float* __restrict__ a, const float* __restrict__ b,
                      const float* __restrict__ c, const float* __restrict__ d) {
    int i = blockIdx.x * blockDim.x + threadIdx.x;
    if (i == 0) { g_totF = 0; g_totP = 0; }
    if (i < SETUP_B1) {
        int n = i >> 11;
        int k = i & (K1_PAD - 1);
        float x = (k < N_GENES) ? w1[(size_t)k * HIDDEN + n] : 0.f;
        __nv_bfloat16 hb = __float2bfloat16(x);
        __nv_bfloat16 lb = __float2bfloat16(x - __bfloat162float(hb));
        size_t addr = (size_t)(k >> 5) * TILE_B + (size_t)n * BROW + (size_t)(k & 31) * 2;
        *reinterpret_cast<__nv_bfloat16*>(g_bt1_hi + addr) = hb;
        *reinterpret_cast<__nv_bfloat16*>(g_bt1_lo + addr) = lb;
    } else if (i < SETUP_B1 + SETUP_B2) {
        int j = i - SETUP_B1;
        int n = j >> 7, k = j & 127;
        const float* s = (n < 128) ? a : (n < 256) ? b : (n < 384) ? c : d;
        float x = s[(size_t)k * 128 + (n & 127)];
        __nv_bfloat16 hb = __float2bfloat16(x);
        __nv_bfloat16 lb = __float2bfloat16(x - __bfloat162float(hb));
        size_t addr = (size_t)((n >> 7) * NC2 + (k >> 5)) * TILE_B
                    + (size_t)(n & 127) * BROW + (size_t)(k & 31) * 2;
        *reinterpret_cast<__nv_bfloat16*>(g_bt2_hi + addr) = hb;
        *reinterpret_cast<__nv_bfloat16*>(g_bt2_lo + addr) = lb;
    } else if (i < SETUP_TOTAL) {
        int n = i - SETUP_B1 - SETUP_B2;
        g_cntF[n] = 0;
        g_cntP[n] = 0;
    }
}

__global__ void count_both(const int* __restrict__ idxF, const int* __restrict__ idxP) {
    int e = blockIdx.x * blockDim.x + threadIdx.x;
    if (e < E_FULL) {
        atomicAdd(&g_cntF[idxF[E_FULL + e]], 1);
    } else {
        int p = e - E_FULL;
        if (p < E_PRUNED) atomicAdd(&g_cntP[idxP[E_PRUNED + p]], 1);
    }
}

// offsets via warp-aggregated atomic allocation (segment ORDER irrelevant, only contiguity)
__global__ void assign_off() {
    int i = blockIdx.x * blockDim.x + threadIdx.x;
    int lane = threadIdx.x & 31;
    bool valid = i < N_CELLS;
    int cF = valid ? g_cntF[i] : 0;
    int cP = valid ? g_cntP[i] : 0;
    int sF = cF, sP = cP;
    #pragma unroll
    for (int o = 1; o < 32; o <<= 1) {
        int tF = __shfl_up_sync(0xffffffffu, sF, o);
        int tP = __shfl_up_sync(0xffffffffu, sP, o);
        if (lane >= o) { sF += tF; sP += tP; }
    }
    int baseF = 0, baseP = 0;
    if (lane == 31) {
        baseF = atomicAdd(&g_totF, sF);
        baseP = atomicAdd(&g_totP, sP);
    }
    baseF = __shfl_sync(0xffffffffu, baseF, 31);
    baseP = __shfl_sync(0xffffffffu, baseP, 31);
    if (valid) {
        int oF = baseF + sF - cF;
        g_offF[i] = oF;
        g_curF[i] = oF;
        int oP = baseP + sP - cP;
        g_offP[i] = oP;
        g_curP[i] = oP;
    }
}

// scatter (src, weight) pairs into CSR order
__global__ void scatter_both(const int* __restrict__ idxF, const float* __restrict__ wF,
                             const int* __restrict__ idxP, const float* __restrict__ wP) {
    int e = blockIdx.x * blockDim.x + threadIdx.x;
    if (e < E_FULL) {
        int dst = idxF[E_FULL + e];
        int pos = atomicAdd(&g_curF[dst], 1);
        g_epF[pos] = make_int2(idxF[e], __float_as_int(wF[e]));
    } else {
        int p = e - E_FULL;
        if (p < E_PRUNED) {
            int dst = idxP[E_PRUNED + p];
            int pos = atomicAdd(&g_curP[dst], 1);
            g_epP[pos] = make_int2(idxP[p], __float_as_int(wP[p]));
        }
    }
}

// ---------------- mma.sync GEMM (split-K capable) ----------------
// fp32 emulation: D += Ah*Bh + Ah*Bl + Al*Bh (bf16 hi/lo split).
__device__ __forceinline__ void load_chunk(const float* __restrict__ A,
                                           const float* __restrict__ A2,
                                           const unsigned char* __restrict__ BH,
                                           const unsigned char* __restrict__ BL,
                                           unsigned char* stg, int tid, long rowBase,
                                           int M, int K, int c, size_t bbase) {
    float4 va[4];
    #pragma unroll
    for (int it = 0; it < 4; it++) {
        int slot = tid + it * 256;
        int r = slot >> 3, kq = slot & 7;
        long gr = rowBase + r;
        int kk = c * 32 + kq * 4;
        va[it] = make_float4(0.f, 0.f, 0.f, 0.f);
        if (gr < M && kk < K) {
            va[it] = __ldg(reinterpret_cast<const float4*>(A + gr * (long)K + kk));
            if (A2) {
                float4 v2 = __ldg(reinterpret_cast<const float4*>(A2 + gr * (long)K + kk));
                va[it].x += v2.x; va[it].y += v2.y; va[it].z += v2.z; va[it].w += v2.w;
            }
        }
    }
    const uint4* bhg = reinterpret_cast<const uint4*>(BH + bbase);
    const uint4* blg = reinterpret_cast<const uint4*>(BL + bbase);
    uint4* sbh = reinterpret_cast<uint4*>(stg + 20480);
    uint4* sbl = reinterpret_cast<uint4*>(stg + 30720);
    for (int j = tid; j < 640; j += 256) {
        sbh[j] = __ldg(bhg + j);
        sbl[j] = __ldg(blg + j);
    }
    #pragma unroll
    for (int it = 0; it < 4; it++) {
        int slot = tid + it * 256;
        int r = slot >> 3, kq = slot & 7;
        float4 v = va[it];
        __nv_bfloat162 h0 = __floats2bfloat162_rn(v.x, v.y);
        __nv_bfloat162 h1 = __floats2bfloat162_rn(v.z, v.w);
        float2 f0 = __bfloat1622float2(h0);
        float2 f1 = __bfloat1622float2(h1);
        __nv_bfloat162 l0 = __floats2bfloat162_rn(v.x - f0.x, v.y - f0.y);
        __nv_bfloat162 l1 = __floats2bfloat162_rn(v.z - f1.x, v.w - f1.y);
        uint32_t off = (uint32_t)r * BROW + (uint32_t)kq * 8;
        *reinterpret_cast<uint2*>(stg + off) =
            make_uint2(*reinterpret_cast<uint32_t*>(&h0), *reinterpret_cast<uint32_t*>(&h1));
        *reinterpret_cast<uint2*>(stg + TILE_B + off) =
            make_uint2(*reinterpret_cast<uint32_t*>(&l0), *reinterpret_cast<uint32_t*>(&l1));
    }
}

// mode: 0 = GEMM1 (A=Xext fp32, B=bt1, C=g_h / g_hB by blockIdx.z, split parts)
//       1 = GEMM2 (A=g_h+g_hB, B=bt2, C=g_hcat)
__global__ void __launch_bounds__(256, 2) gemm_mma(const float* __restrict__ Aext,
                                                   const float* __restrict__ bias,
                                                   int mode, int M, int K, int NCols,
                                                   int NChunks, int parts) {
    extern __shared__ unsigned char smp[];
    const float* A = mode ? g_h : Aext;
    const float* A2 = mode ? g_hB : nullptr;
    const unsigned char* BH = mode ? g_bt2_hi : g_bt1_hi;
    const unsigned char* BL = mode ? g_bt2_lo : g_bt1_lo;
    int z = blockIdx.z;
    float* C = mode ? g_hcat : (z ? g_hB : g_h);
    const float* biasp = (bias && z == 0) ? bias : nullptr;

    int tid = threadIdx.x;
    int lane = tid & 31;
    int wid = tid >> 5;
    int warpM = wid & 1;
    int warpN = wid >> 1;
    long rowBase = (long)blockIdx.y * 128;
    int nTile = blockIdx.x;
    int colBase = nTile * 128;
    size_t bTileBase = (size_t)nTile * NChunks * TILE_B;

    int cpp = NChunks / parts;
    int c0 = z * cpp, c1 = c0 + cpp;

    float acc[4][4][4];
    #pragma unroll
    for (int mi = 0; mi < 4; mi++)
        #pragma unroll
        for (int ni = 0; ni < 4; ni++)
            #pragma unroll
            for (int q = 0; q < 4; q++) acc[mi][ni][q] = 0.f;

    uint32_t sbase0 = smem_u32(smp);
    uint32_t aoff = (uint32_t)(((lane & 7) + ((lane >> 3) & 1) * 8) * BROW + (lane >> 4) * 16);
    uint32_t boff = (uint32_t)((lane & 7) * BROW + ((lane >> 3) & 1) * 16);

    load_chunk(A, A2, BH, BL, smp, tid, rowBase, M, K, c0, bTileBase + (size_t)c0 * TILE_B);

    for (int c = c0; c < c1; c++) {
        __syncthreads();
        int rc = c - c0;
        int nc = c + 1;
        if (nc < c1)
            load_chunk(A, A2, BH, BL, smp + ((rc + 1) & 1) * STAGE_B, tid, rowBase, M, K, nc,
                       bTileBase + (size_t)nc * TILE_B);

        uint32_t sb = sbase0 + (rc & 1) * STAGE_B;
        uint32_t sAh = sb, sAl = sb + TILE_B, sBh = sb + 20480, sBl = sb + 30720;
        #pragma unroll
        for (int ks = 0; ks < 2; ks++) {
            uint32_t kb = ks * 32;
            uint32_t ah[4][4], al[4][4], bh[4][2], bl[4][2];
            #pragma unroll
            for (int mi = 0; mi < 4; mi++) {
                uint32_t base = (uint32_t)((warpM * 64 + mi * 16) * BROW) + kb + aoff;
                ldsm_x4(ah[mi], sAh + base);
                ldsm_x4(al[mi], sAl + base);
            }
            #pragma unroll
            for (int ni = 0; ni < 4; ni++) {
                uint32_t base = (uint32_t)((warpN * 32 + ni * 8) * BROW) + kb + boff;
                ldsm_x2(bh[ni], sBh + base);
                ldsm_x2(bl[ni], sBl + base);
            }
            #pragma unroll
            for (int mi = 0; mi < 4; mi++)
                #pragma unroll
                for (int ni = 0; ni < 4; ni++) {
                    mma_bf16(acc[mi][ni], ah[mi], bh[ni]);
                    mma_bf16(acc[mi][ni], ah[mi], bl[ni]);
                    mma_bf16(acc[mi][ni], al[mi], bh[ni]);
                }
        }
    }

    #pragma unroll
    for (int mi = 0; mi < 4; mi++) {
        #pragma unroll
        for (int ni = 0; ni < 4; ni++) {
            long r0 = rowBase + warpM * 64 + mi * 16 + (lane >> 2);
            int col = colBase + warpN * 32 + ni * 8 + (lane & 3) * 2;
            float b0 = 0.f, b1 = 0.f;
            if (biasp) { b0 = __ldg(&biasp[col]); b1 = __ldg(&biasp[col + 1]); }
            if (r0 < M) {
                float2 v = make_float2(acc[mi][ni][0] + b0, acc[mi][ni][1] + b1);
                *reinterpret_cast<float2*>(C + r0 * (long)NCols + col) = v;
            }
            long r1 = r0 + 8;
            if (r1 < M) {
                float2 v = make_float2(acc[mi][ni][2] + b0, acc[mi][ni][3] + b1);
                *reinterpret_cast<float2*>(C + r1 * (long)NCols + col) = v;
            }
        }
    }
}

// ---------------- fused GAT aggregation + combine + ELU + LayerNorm ----------------
__global__ void __launch_bounds__(256) gat_finalize(
    const float* __restrict__ alpha_p,
    const float* __restrict__ weF, const float* __restrict__ atF, const float* __restrict__ biF,
    const float* __restrict__ weP, const float* __restrict__ atP, const float* __restrict__ biP,
    const float* __restrict__ lnS, const float* __restrict__ lnB,
    float* __restrict__ out) {
    int gw = (blockIdx.x * blockDim.x + threadIdx.x) >> 5;
    int lane = threadIdx.x & 31;
    if (gw >= N_CELLS) return;

    const float4* hc = reinterpret_cast<const float4*>(g_hcat);
    size_t row = (size_t)gw * 128;

    float4 hdF = __ldg(hc + row + 32 + lane);
    float4 hdP = __ldg(hc + row + 96 + lane);
    float4 vweF = __ldg(reinterpret_cast<const float4*>(weF) + lane);
    float4 vatF = __ldg(reinterpret_cast<const float4*>(atF) + lane);
    float4 vweP = __ldg(reinterpret_cast<const float4*>(weP) + lane);
    float4 vatP = __ldg(reinterpret_cast<const float4*>(atP) + lane);

    int sF = __ldg(&g_offF[gw]), nF = __ldg(&g_cntF[gw]);
    int sP = __ldg(&g_offP[gw]), nP = __ldg(&g_cntP[gw]);

    float4 accF = make_float4(0.f, 0.f, 0.f, 0.f);
    float4 accP = make_float4(0.f, 0.f, 0.f, 0.f);
    float denF = 0.f, denP = 0.f;

    int nmax = nF > nP ? nF : nP;
    for (int i = 0; i < nmax; i++) {
        if (i < nF) {
            int2 pe = __ldg(&g_epF[sF + i]);
            float we = __int_as_float(pe.y);
            float4 hs = __ldg(hc + (size_t)pe.x * 128 + lane);
            float4 z;
            z.x = fmaf(we, vweF.x, hs.x + hdF.x);
            z.y = fmaf(we, vweF.y, hs.y + hdF.y);
            z.z = fmaf(we, vweF.z, hs.z + hdF.z);
            z.w = fmaf(we, vweF.w, hs.w + hdF.w);
            z.x = fmaxf(z.x, 0.2f * z.x);
            z.y = fmaxf(z.y, 0.2f * z.y);
            z.z = fmaxf(z.z, 0.2f * z.z);
            z.w = fmaxf(z.w, 0.2f * z.w);
            float p = z.x * vatF.x + z.y * vatF.y + z.z * vatF.z + z.w * vatF.w;
            p += __shfl_xor_sync(0xffffffffu, p, 1);
            p += __shfl_xor_sync(0xffffffffu, p, 2);
            p += __shfl_xor_sync(0xffffffffu, p, 4);
            float ex = __expf(p);
            denF += ex;
            accF.x = fmaf(ex, hs.x, accF.x);
            accF.y = fmaf(ex, hs.y, accF.y);
            accF.z = fmaf(ex, hs.z, accF.z);
            accF.w = fmaf(ex, hs.w, accF.w);
        }
        if (i < nP) {
            int2 pe = __ldg(&g_epP[sP + i]);
            float we = __int_as_float(pe.y);
            float4 hs = __ldg(hc + (size_t)pe.x * 128 + 64 + lane);
            float4 z;
            z.x = fmaf(we, vweP.x, hs.x + hdP.x);
            z.y = fmaf(we, vweP.y, hs.y + hdP.y);
            z.z = fmaf(we, vweP.z, hs.z + hdP.z);
            z.w = fmaf(we, vweP.w, hs.w + hdP.w);
            z.x = fmaxf(z.x, 0.2f * z.x);
            z.y = fmaxf(z.y, 0.2f * z.y);
            z.z = fmaxf(z.z, 0.2f * z.z);
            z.w = fmaxf(z.w, 0.2f * z.w);
            float p = z.x * vatP.x + z.y * vatP.y + z.z * vatP.z + z.w * vatP.w;
            p += __shfl_xor_sync(0xffffffffu, p, 1);
            p += __shfl_xor_sync(0xffffffffu, p, 2);
            p += __shfl_xor_sync(0xffffffffu, p, 4);
            float ex = __expf(p);
            denP += ex;
            accP.x = fmaf(ex, hs.x, accP.x);
            accP.y = fmaf(ex, hs.y, accP.y);
            accP.z = fmaf(ex, hs.z, accP.z);
            accP.w = fmaf(ex, hs.w, accP.w);
        }
    }

    float alpha = __ldg(alpha_p);
    float rdF = 1.f / (denF + 1e-16f);
    float rdP = 1.f / (denP + 1e-16f);
    float4 bF = __ldg(reinterpret_cast<const float4*>(biF) + lane);
    float4 bP = __ldg(reinterpret_cast<const float4*>(biP) + lane);
    float a1 = 1.f - alpha;

    float4 r;
    r.x = a1 * (accF.x * rdF + bF.x) + alpha * (accP.x * rdP + bP.x);
    r.y = a1 * (accF.y * rdF + bF.y) + alpha * (accP.y * rdP + bP.y);
    r.z = a1 * (accF.z * rdF + bF.z) + alpha * (accP.z * rdP + bP.z);
    r.w = a1 * (accF.w * rdF + bF.w) + alpha * (accP.w * rdP + bP.w);

    r.x = r.x > 0.f ? r.x : expm1f(r.x);
    r.y = r.y > 0.f ? r.y : expm1f(r.y);
    r.z = r.z > 0.f ? r.z : expm1f(r.z);
    r.w = r.w > 0.f ? r.w : expm1f(r.w);

    float sum = r.x + r.y + r.z + r.w;
    #pragma unroll
    for (int o = 16; o >= 1; o >>= 1) sum += __shfl_xor_sync(0xffffffffu, sum, o);
    float mu = sum * (1.f / 128.f);
    float4 d;
    d.x = r.x - mu; d.y = r.y - mu; d.z = r.z - mu; d.w = r.w - mu;
    float sq = d.x * d.x + d.y * d.y + d.z * d.z + d.w * d.w;
    #pragma unroll
    for (int o = 16; o >= 1; o >>= 1) sq += __shfl_xor_sync(0xffffffffu, sq, o);
    float rstd = rsqrtf(sq * (1.f / 128.f) + 1e-6f);
    float4 s4 = __ldg(reinterpret_cast<const float4*>(lnS) + lane);
    float4 b4 = __ldg(reinterpret_cast<const float4*>(lnB) + lane);
    float4 o;
    o.x = d.x * rstd * s4.x + b4.x;
    o.y = d.y * rstd * s4.y + b4.y;
    o.z = d.z * rstd * s4.z + b4.z;
    o.w = d.w * rstd * s4.w + b4.w;
    reinterpret_cast<float4*>(out)[(size_t)gw * 32 + lane] = o;
}

// ---------------- host orchestration ----------------
extern "C" void kernel_launch(void* const* d_in, const int* in_sizes, int n_in,
                              void* d_out, int out_size) {
    const float* X        = (const float*)d_in[0];
    const int*   idxF     = (const int*)d_in[1];
    const float* wF       = (const float*)d_in[2];
    const int*   idxP     = (const int*)d_in[3];
    const float* wP       = (const float*)d_in[4];
    const float* alpha    = (const float*)d_in[5];
    const float* ip_w     = (const float*)d_in[6];
    const float* ip_b     = (const float*)d_in[7];
    const float* gf_wsrc  = (const float*)d_in[8];
    const float* gf_wdst  = (const float*)d_in[9];
    const float* gf_wedge = (const float*)d_in[10];
    const float* gf_attn  = (const float*)d_in[11];
    const float* gf_bias  = (const float*)d_in[12];
    const float* gp_wsrc  = (const float*)d_in[13];
    const float* gp_wdst  = (const float*)d_in[14];
    const float* gp_wedge = (const float*)d_in[15];
    const float* gp_attn  = (const float*)d_in[16];
    const float* gp_bias  = (const float*)d_in[17];
    const float* ln_scale = (const float*)d_in[18];
    const float* ln_bias  = (const float*)d_in[19];
    float* out = (float*)d_out;

    cudaFuncSetAttribute(gemm_mma, cudaFuncAttributeMaxDynamicSharedMemorySize, SMEM_DYN);

    setup<<<(SETUP_TOTAL + 255) / 256, 256>>>(ip_w, gf_wsrc, gf_wdst, gp_wsrc, gp_wdst);  // 1
    count_both<<<(E_FULL + E_PRUNED + 255) / 256, 256>>>(idxF, idxP);                     // 2
    assign_off<<<(N_CELLS + 255) / 256, 256>>>();                                         // 3

    // h = X @ ip_w + ip_b, split-K=2: z=0 -> g_h (+bias), z=1 -> g_hB
    gemm_mma<<<dim3(1, (N_CELLS + 127) / 128, 2), 256, SMEM_DYN>>>(
        X, ip_b, /*mode=*/0, N_CELLS, N_GENES, HIDDEN, NC1, /*parts=*/2);                 // 4
    // hcat = (g_h + g_hB) @ [wsrcF|wdstF|wsrcP|wdstP]
    gemm_mma<<<dim3(4, (N_CELLS + 127) / 128, 1), 256, SMEM_DYN>>>(
        nullptr, nullptr, /*mode=*/1, N_CELLS, HIDDEN, 512, NC2, /*parts=*/1);            // 5

    scatter_both<<<(E_FULL + E_PRUNED + 255) / 256, 256>>>(idxF, wF, idxP, wP);           // 6

    gat_finalize<<<(N_CELLS * 32 + 255) / 256, 256>>>(alpha,
                                                      gf_wedge, gf_attn, gf_bias,
                                                      gp_wedge, gp_attn, gp_bias,
                                                      ln_scale, ln_bias, out);            // 7
}

// round 8
// speedup vs baseline: 1.4385x; 1.4385x over previous
#include <cuda_runtime.h>
#include <cuda_bf16.h>
#include <cstdint>

#define N_CELLS 50000
#define N_GENES 2000
#define HIDDEN 128
#define E_FULL 800000
#define E_PRUNED 400000
#define K1_PAD 2048
#define NC1 64            // K chunks (BK=32) for GEMM1
#define NC2 4             // K chunks for GEMM2
#define BK 32
#define BROW 80           // padded SMEM row stride (32 bf16 + 8 pad) bytes
#define TILE_B 10240      // 128 rows * 80 B (bf16 tile, hi or lo)
#define STAGE_IN 36864    // A32 (16384) + Bh (10240) + Bl (10240)
#define ABF_OFF 73728     // after 2 input stages: Ah (10240) + Al (10240)
#define SMEM_DYN (ABF_OFF + 2 * TILE_B)   // 94208

// ---------------- device scratch (allocation-free) ----------------
__device__ float g_h[(size_t)N_CELLS * HIDDEN];
__device__ float g_hcat[(size_t)N_CELLS * 512];   // [hsF|hdF|hsP|hdP]
__device__ __align__(16) unsigned char g_bt1_hi[(size_t)NC1 * TILE_B];
__device__ __align__(16) unsigned char g_bt1_lo[(size_t)NC1 * TILE_B];
__device__ __align__(16) unsigned char g_bt2_hi[(size_t)4 * NC2 * TILE_B];
__device__ __align__(16) unsigned char g_bt2_lo[(size_t)4 * NC2 * TILE_B];
__device__ int g_cntF[N_CELLS], g_cntP[N_CELLS];
__device__ int g_offF[N_CELLS], g_offP[N_CELLS];
__device__ int g_curF[N_CELLS], g_curP[N_CELLS];
__device__ int g_totF, g_totP;
__device__ int2 g_epF[E_FULL], g_epP[E_PRUNED];   // (src, weight-bits) in CSR order

// ---------------- helpers ----------------
__device__ __forceinline__ uint32_t smem_u32(const void* p) {
    uint32_t a;
    asm("{ .reg .u64 t; cvta.to.shared.u64 t, %1; cvt.u32.u64 %0, t; }" : "=r"(a) : "l"(p));
    return a;
}
__device__ __forceinline__ void ldsm_x4(uint32_t* r, uint32_t a) {
    asm volatile("ldmatrix.sync.aligned.m8n8.x4.shared.b16 {%0,%1,%2,%3}, [%4];"
                 : "=r"(r[0]), "=r"(r[1]), "=r"(r[2]), "=r"(r[3]) : "r"(a));
}
__device__ __forceinline__ void ldsm_x2(uint32_t* r, uint32_t a) {
    asm volatile("ldmatrix.sync.aligned.m8n8.x2.shared.b16 {%0,%1}, [%2];"
                 : "=r"(r[0]), "=r"(r[1]) : "r"(a));
}
__device__ __forceinline__ void mma_bf16(float* d, const uint32_t* a, const uint32_t* b) {
    asm volatile("mma.sync.aligned.m16n8k16.row.col.f32.bf16.bf16.f32 "
                 "{%0,%1,%2,%3}, {%4,%5,%6,%7}, {%8,%9}, {%0,%1,%2,%3};"
                 : "+f"(d[0]), "+f"(d[1]), "+f"(d[2]), "+f"(d[3])
                 : "r"(a[0]), "r"(a[1]), "r"(a[2]), "r"(a[3]), "r"(b[0]), "r"(b[1]));
}
__device__ __forceinline__ void cp16(uint32_t dst, const void* src, int vbytes) {
    asm volatile("cp.async.cg.shared.global [%0], [%1], 16, %2;"
                 :: "r"(dst), "l"(src), "r"(vbytes) : "memory");
}
__device__ __forceinline__ void cp16f(uint32_t dst, const void* src) {
    asm volatile("cp.async.cg.shared.global [%0], [%1], 16;"
                 :: "r"(dst), "l"(src) : "memory");
}
#define CP_COMMIT() asm volatile("cp.async.commit_group;" ::: "memory")
#define CP_WAIT1()  asm volatile("cp.async.wait_group 1;" ::: "memory")

// ---------------- setup: zero counters + pack B1 + pack B2 ----------------
#define SETUP_B1 (128 * K1_PAD)
#define SETUP_B2 (512 * 128)
#define SETUP_TOTAL (SETUP_B1 + SETUP_B2 + N_CELLS)
__global__ void setup(const float* __restrict__ w1,
                      const float* __restrict__ a, const float* __restrict__ b,
                      const float* __restrict__ c, const float* __restrict__ d) {
    int i = blockIdx.x * blockDim.x + threadIdx.x;
    if (i == 0) { g_totF = 0; g_totP = 0; }
    if (i < SETUP_B1) {
        int n = i >> 11;
        int k = i & (K1_PAD - 1);
        float x = (k < N_GENES) ? w1[(size_t)k * HIDDEN + n] : 0.f;
        __nv_bfloat16 hb = __float2bfloat16(x);
        __nv_bfloat16 lb = __float2bfloat16(x - __bfloat162float(hb));
        size_t addr = (size_t)(k >> 5) * TILE_B + (size_t)n * BROW + (size_t)(k & 31) * 2;
        *reinterpret_cast<__nv_bfloat16*>(g_bt1_hi + addr) = hb;
        *reinterpret_cast<__nv_bfloat16*>(g_bt1_lo + addr) = lb;
    } else if (i < SETUP_B1 + SETUP_B2) {
        int j = i - SETUP_B1;
        int n = j >> 7, k = j & 127;
        const float* s = (n < 128) ? a : (n < 256) ? b : (n < 384) ? c : d;
        float x = s[(size_t)k * 128 + (n & 127)];
        __nv_bfloat16 hb = __float2bfloat16(x);
        __nv_bfloat16 lb = __float2bfloat16(x - __bfloat162float(hb));
        size_t addr = (size_t)((n >> 7) * NC2 + (k >> 5)) * TILE_B
                    + (size_t)(n & 127) * BROW + (size_t)(k & 31) * 2;
        *reinterpret_cast<__nv_bfloat16*>(g_bt2_hi + addr) = hb;
        *reinterpret_cast<__nv_bfloat16*>(g_bt2_lo + addr) = lb;
    } else if (i < SETUP_TOTAL) {
        int n = i - SETUP_B1 - SETUP_B2;
        g_cntF[n] = 0;
        g_cntP[n] = 0;
    }
}

__global__ void count_both(const int* __restrict__ idxF, const int* __restrict__ idxP) {
    int e = blockIdx.x * blockDim.x + threadIdx.x;
    if (e < E_FULL) {
        atomicAdd(&g_cntF[idxF[E_FULL + e]], 1);
    } else {
        int p = e - E_FULL;
        if (p < E_PRUNED) atomicAdd(&g_cntP[idxP[E_PRUNED + p]], 1);
    }
}

// offsets via warp-aggregated atomic allocation (segment ORDER irrelevant)
__global__ void assign_off() {
    int i = blockIdx.x * blockDim.x + threadIdx.x;
    int lane = threadIdx.x & 31;
    bool valid = i < N_CELLS;
    int cF = valid ? g_cntF[i] : 0;
    int cP = valid ? g_cntP[i] : 0;
    int sF = cF, sP = cP;
    #pragma unroll
    for (int o = 1; o < 32; o <<= 1) {
        int tF = __shfl_up_sync(0xffffffffu, sF, o);
        int tP = __shfl_up_sync(0xffffffffu, sP, o);
        if (lane >= o) { sF += tF; sP += tP; }
    }
    int baseF = 0, baseP = 0;
    if (lane == 31) {
        baseF = atomicAdd(&g_totF, sF);
        baseP = atomicAdd(&g_totP, sP);
    }
    baseF = __shfl_sync(0xffffffffu, baseF, 31);
    baseP = __shfl_sync(0xffffffffu, baseP, 31);
    if (valid) {
        int oF = baseF + sF - cF;
        g_offF[i] = oF;
        g_curF[i] = oF;
        int oP = baseP + sP - cP;
        g_offP[i] = oP;
        g_curP[i] = oP;
    }
}

__global__ void scatter_both(const int* __restrict__ idxF, const float* __restrict__ wF,
                             const int* __restrict__ idxP, const float* __restrict__ wP) {
    int e = blockIdx.x * blockDim.x + threadIdx.x;
    if (e < E_FULL) {
        int dst = idxF[E_FULL + e];
        int pos = atomicAdd(&g_curF[dst], 1);
        g_epF[pos] = make_int2(idxF[e], __float_as_int(wF[e]));
    } else {
        int p = e - E_FULL;
        if (p < E_PRUNED) {
            int dst = idxP[E_PRUNED + p];
            int pos = atomicAdd(&g_curP[dst], 1);
            g_epP[pos] = make_int2(idxP[p], __float_as_int(wP[p]));
        }
    }
}

// ---------------- cp.async pipelined mma.sync GEMM ----------------
// A fp32 streamed via cp.async into SMEM ring, converted to bf16 hi/lo in SMEM,
// fp32 emulation: D += Ah*Bh + Ah*Bl + Al*Bh.
__device__ __forceinline__ void cp_issue(const float* __restrict__ A,
                                         const unsigned char* __restrict__ BH,
                                         const unsigned char* __restrict__ BL,
                                         uint32_t stage, int tid, long rowBase,
                                         int M, int K, int c, size_t bbase) {
    #pragma unroll
    for (int it = 0; it < 4; it++) {
        int slot = tid + it * 256;           // 1024 16B slots of A (128 rows x 8)
        int r = slot >> 3, kq = slot & 7;
        long gr = rowBase + r;
        int kk = c * BK + kq * 4;
        int vb = 16;
        if (gr >= M) { gr = 0; vb = 0; }
        int rem = (K - kk) * 4;
        if (rem < 16) { vb = (rem > 0) ? ((vb < rem) ? vb : rem) : 0; if (rem <= 0) kk = 0; }
        uint32_t dst = stage + (uint32_t)(r * 128 + ((kq ^ (r & 7)) << 4));
        cp16(dst, A + gr * (long)K + kk, vb);
    }
    #pragma unroll
    for (int it = 0; it < 3; it++) {
        int j = tid + it * 256;              // 640 16B slots per B tile
        if (j < 640) {
            cp16f(stage + 16384 + (uint32_t)j * 16, BH + bbase + (size_t)j * 16);
            cp16f(stage + 26624 + (uint32_t)j * 16, BL + bbase + (size_t)j * 16);
        }
    }
}

__global__ void __launch_bounds__(256, 2) gemm_mma(const float* __restrict__ Aext,
                                                   const float* __restrict__ bias,
                                                   int mode, int M, int K, int NCols,
                                                   int NChunks) {
    extern __shared__ __align__(128) unsigned char smp[];
    const float* A = mode ? g_h : Aext;
    const unsigned char* BH = mode ? g_bt2_hi : g_bt1_hi;
    const unsigned char* BL = mode ? g_bt2_lo : g_bt1_lo;
    float* C = mode ? g_hcat : g_h;

    int tid = threadIdx.x;
    int lane = tid & 31;
    int wid = tid >> 5;
    int warpM = wid & 1;
    int warpN = wid >> 1;
    long rowBase = (long)blockIdx.y * 128;
    int nTile = blockIdx.x;
    int colBase = nTile * 128;
    size_t bTileBase = (size_t)nTile * NChunks * TILE_B;

    float acc[4][4][4];
    #pragma unroll
    for (int mi = 0; mi < 4; mi++)
        #pragma unroll
        for (int ni = 0; ni < 4; ni++)
            #pragma unroll
            for (int q = 0; q < 4; q++) acc[mi][ni][q] = 0.f;

    uint32_t sbase = smem_u32(smp);
    uint32_t aoff = (uint32_t)(((lane & 7) + ((lane >> 3) & 1) * 8) * BROW + (lane >> 4) * 16);
    uint32_t boff = (uint32_t)((lane & 7) * BROW + ((lane >> 3) & 1) * 16);
    uint32_t sAh = sbase + ABF_OFF;
    uint32_t sAl = sAh + TILE_B;

    cp_issue(A, BH, BL, sbase, tid, rowBase, M, K, 0, bTileBase);
    CP_COMMIT();

    for (int c = 0; c < NChunks; c++) {
        __syncthreads();   // MMA(c-1) done reading B stage & Abf before overwrite
        int nc = c + 1;
        if (nc < NChunks)
            cp_issue(A, BH, BL, sbase + (nc & 1) * STAGE_IN, tid, rowBase, M, K, nc,
                     bTileBase + (size_t)nc * TILE_B);
        CP_COMMIT();
        CP_WAIT1();        // chunk c's data arrived
        __syncthreads();

        // convert A fp32 (SMEM) -> bf16 hi/lo (SMEM)
        uint32_t stOff = (uint32_t)(c & 1) * STAGE_IN;
        #pragma unroll
        for (int it = 0; it < 4; it++) {
            int slot = tid + it * 256;
            int r = slot >> 3, kq = slot & 7;
            float4 v = *reinterpret_cast<const float4*>(
                smp + stOff + r * 128 + ((kq ^ (r & 7)) << 4));
            __nv_bfloat162 h0 = __floats2bfloat162_rn(v.x, v.y);
            __nv_bfloat162 h1 = __floats2bfloat162_rn(v.z, v.w);
            float2 f0 = __bfloat1622float2(h0);
            float2 f1 = __bfloat1622float2(h1);
            __nv_bfloat162 l0 = __floats2bfloat162_rn(v.x - f0.x, v.y - f0.y);
            __nv_bfloat162 l1 = __floats2bfloat162_rn(v.z - f1.x, v.w - f1.y);
            uint32_t off = (uint32_t)r * BROW + (uint32_t)kq * 8;
            *reinterpret_cast<uint2*>(smp + ABF_OFF + off) =
                make_uint2(*reinterpret_cast<uint32_t*>(&h0), *reinterpret_cast<uint32_t*>(&h1));
            *reinterpret_cast<uint2*>(smp + ABF_OFF + TILE_B + off) =
                make_uint2(*reinterpret_cast<uint32_t*>(&l0), *reinterpret_cast<uint32_t*>(&l1));
        }
        __syncthreads();

        uint32_t sBh = sbase + stOff + 16384;
        uint32_t sBl = sbase + stOff + 26624;
        #pragma unroll
        for (int ks = 0; ks < 2; ks++) {
            uint32_t kb = ks * 32;
            uint32_t ah[4][4], al[4][4], bh[4][2], bl[4][2];
            #pragma unroll
            for (int mi = 0; mi < 4; mi++) {
                uint32_t base = (uint32_t)((warpM * 64 + mi * 16) * BROW) + kb + aoff;
                ldsm_x4(ah[mi], sAh + base);
                ldsm_x4(al[mi], sAl + base);
            }
            #pragma unroll
            for (int ni = 0; ni < 4; ni++) {
                uint32_t base = (uint32_t)((warpN * 32 + ni * 8) * BROW) + kb + boff;
                ldsm_x2(bh[ni], sBh + base);
                ldsm_x2(bl[ni], sBl + base);
            }
            #pragma unroll
            for (int mi = 0; mi < 4; mi++)
                #pragma unroll
                for (int ni = 0; ni < 4; ni++) {
                    mma_bf16(acc[mi][ni], ah[mi], bh[ni]);
                    mma_bf16(acc[mi][ni], ah[mi], bl[ni]);
                    mma_bf16(acc[mi][ni], al[mi], bh[ni]);
                }
        }
    }

    #pragma unroll
    for (int mi = 0; mi < 4; mi++) {
        #pragma unroll
        for (int ni = 0; ni < 4; ni++) {
            long r0 = rowBase + warpM * 64 + mi * 16 + (lane >> 2);
            int col = colBase + warpN * 32 + ni * 8 + (lane & 3) * 2;
            float b0 = 0.f, b1 = 0.f;
            if (bias) { b0 = __ldg(&bias[col]); b1 = __ldg(&bias[col + 1]); }
            if (r0 < M) {
                float2 v = make_float2(acc[mi][ni][0] + b0, acc[mi][ni][1] + b1);
                *reinterpret_cast<float2*>(C + r0 * (long)NCols + col) = v;
            }
            long r1 = r0 + 8;
            if (r1 < M) {
                float2 v = make_float2(acc[mi][ni][2] + b0, acc[mi][ni][3] + b1);
                *reinterpret_cast<float2*>(C + r1 * (long)NCols + col) = v;
            }
        }
    }
}

// ---------------- fused GAT aggregation + combine + ELU + LayerNorm ----------------
__global__ void __launch_bounds__(256) gat_finalize(
    const float* __restrict__ alpha_p,
    const float* __restrict__ weF, const float* __restrict__ atF, const float* __restrict__ biF,
    const float* __restrict__ weP, const float* __restrict__ atP, const float* __restrict__ biP,
    const float* __restrict__ lnS, const float* __restrict__ lnB,
    float* __restrict__ out) {
    int gw = (blockIdx.x * blockDim.x + threadIdx.x) >> 5;
    int lane = threadIdx.x & 31;
    if (gw >= N_CELLS) return;

    const float4* hc = reinterpret_cast<const float4*>(g_hcat);
    size_t row = (size_t)gw * 128;

    float4 hdF = __ldg(hc + row + 32 + lane);
    float4 hdP = __ldg(hc + row + 96 + lane);
    float4 vweF = __ldg(reinterpret_cast<const float4*>(weF) + lane);
    float4 vatF = __ldg(reinterpret_cast<const float4*>(atF) + lane);
    float4 vweP = __ldg(reinterpret_cast<const float4*>(weP) + lane);
    float4 vatP = __ldg(reinterpret_cast<const float4*>(atP) + lane);

    int sF = __ldg(&g_offF[gw]), nF = __ldg(&g_cntF[gw]);
    int sP = __ldg(&g_offP[gw]), nP = __ldg(&g_cntP[gw]);

    float4 accF = make_float4(0.f, 0.f, 0.f, 0.f);
    float4 accP = make_float4(0.f, 0.f, 0.f, 0.f);
    float denF = 0.f, denP = 0.f;

    int nmax = nF > nP ? nF : nP;
    for (int i = 0; i < nmax; i++) {
        if (i < nF) {
            int2 pe = __ldg(&g_epF[sF + i]);
            float we = __int_as_float(pe.y);
            float4 hs = __ldg(hc + (size_t)pe.x * 128 + lane);
            float4 z;
            z.x = fmaf(we, vweF.x, hs.x + hdF.x);
            z.y = fmaf(we, vweF.y, hs.y + hdF.y);
            z.z = fmaf(we, vweF.z, hs.z + hdF.z);
            z.w = fmaf(we, vweF.w, hs.w + hdF.w);
            z.x = fmaxf(z.x, 0.2f * z.x);
            z.y = fmaxf(z.y, 0.2f * z.y);
            z.z = fmaxf(z.z, 0.2f * z.z);
            z.w = fmaxf(z.w, 0.2f * z.w);
            float p = z.x * vatF.x + z.y * vatF.y + z.z * vatF.z + z.w * vatF.w;
            p += __shfl_xor_sync(0xffffffffu, p, 1);
            p += __shfl_xor_sync(0xffffffffu, p, 2);
            p += __shfl_xor_sync(0xffffffffu, p, 4);
            float ex = __expf(p);
            denF += ex;
            accF.x = fmaf(ex, hs.x, accF.x);
            accF.y = fmaf(ex, hs.y, accF.y);
            accF.z = fmaf(ex, hs.z, accF.z);
            accF.w = fmaf(ex, hs.w, accF.w);
        }
        if (i < nP) {
            int2 pe = __ldg(&g_epP[sP + i]);
            float we = __int_as_float(pe.y);
            float4 hs = __ldg(hc + (size_t)pe.x * 128 + 64 + lane);
            float4 z;
            z.x = fmaf(we, vweP.x, hs.x + hdP.x);
            z.y = fmaf(we, vweP.y, hs.y + hdP.y);
            z.z = fmaf(we, vweP.z, hs.z + hdP.z);
            z.w = fmaf(we, vweP.w, hs.w + hdP.w);
            z.x = fmaxf(z.x, 0.2f * z.x);
            z.y = fmaxf(z.y, 0.2f * z.y);
            z.z = fmaxf(z.z, 0.2f * z.z);
            z.w = fmaxf(z.w, 0.2f * z.w);
            float p = z.x * vatP.x + z.y * vatP.y + z.z * vatP.z + z.w * vatP.w;
            p += __shfl_xor_sync(0xffffffffu, p, 1);
            p += __shfl_xor_sync(0xffffffffu, p, 2);
            p += __shfl_xor_sync(0xffffffffu, p, 4);
            float ex = __expf(p);
            denP += ex;
            accP.x = fmaf(ex, hs.x, accP.x);
            accP.y = fmaf(ex, hs.y, accP.y);
            accP.z = fmaf(ex, hs.z, accP.z);
            accP.w = fmaf(ex, hs.w, accP.w);
        }
    }

    float alpha = __ldg(alpha_p);
    float rdF = 1.f / (denF + 1e-16f);
    float rdP = 1.f / (denP + 1e-16f);
    float4 bF = __ldg(reinterpret_cast<const float4*>(biF) + lane);
    float4 bP = __ldg(reinterpret_cast<const float4*>(biP) + lane);
    float a1 = 1.f - alpha;

    float4 r;
    r.x = a1 * (accF.x * rdF + bF.x) + alpha * (accP.x * rdP + bP.x);
    r.y = a1 * (accF.y * rdF + bF.y) + alpha * (accP.y * rdP + bP.y);
    r.z = a1 * (accF.z * rdF + bF.z) + alpha * (accP.z * rdP + bP.z);
    r.w = a1 * (accF.w * rdF + bF.w) + alpha * (accP.w * rdP + bP.w);

    r.x = r.x > 0.f ? r.x : expm1f(r.x);
    r.y = r.y > 0.f ? r.y : expm1f(r.y);
    r.z = r.z > 0.f ? r.z : expm1f(r.z);
    r.w = r.w > 0.f ? r.w : expm1f(r.w);

    float sum = r.x + r.y + r.z + r.w;
    #pragma unroll
    for (int o = 16; o >= 1; o >>= 1) sum += __shfl_xor_sync(0xffffffffu, sum, o);
    float mu = sum * (1.f / 128.f);
    float4 d;
    d.x = r.x - mu; d.y = r.y - mu; d.z = r.z - mu; d.w = r.w - mu;
    float sq = d.x * d.x + d.y * d.y + d.z * d.z + d.w * d.w;
    #pragma unroll
    for (int o = 16; o >= 1; o >>= 1) sq += __shfl_xor_sync(0xffffffffu, sq, o);
    float rstd = rsqrtf(sq * (1.f / 128.f) + 1e-6f);
    float4 s4 = __ldg(reinterpret_cast<const float4*>(lnS) + lane);
    float4 b4 = __ldg(reinterpret_cast<const float4*>(lnB) + lane);
    float4 o;
    o.x = d.x * rstd * s4.x + b4.x;
    o.y = d.y * rstd * s4.y + b4.y;
    o.z = d.z * rstd * s4.z + b4.z;
    o.w = d.w * rstd * s4.w + b4.w;
    reinterpret_cast<float4*>(out)[(size_t)gw * 32 + lane] = o;
}

// ---------------- host orchestration ----------------
extern "C" void kernel_launch(void* const* d_in, const int* in_sizes, int n_in,
                              void* d_out, int out_size) {
    const float* X        = (const float*)d_in[0];
    const int*   idxF     = (const int*)d_in[1];
    const float* wF       = (const float*)d_in[2];
    const int*   idxP     = (const int*)d_in[3];
    const float* wP       = (const float*)d_in[4];
    const float* alpha    = (const float*)d_in[5];
    const float* ip_w     = (const float*)d_in[6];
    const float* ip_b     = (const float*)d_in[7];
    const float* gf_wsrc  = (const float*)d_in[8];
    const float* gf_wdst  = (const float*)d_in[9];
    const float* gf_wedge = (const float*)d_in[10];
    const float* gf_attn  = (const float*)d_in[11];
    const float* gf_bias  = (const float*)d_in[12];
    const float* gp_wsrc  = (const float*)d_in[13];
    const float* gp_wdst  = (const float*)d_in[14];
    const float* gp_wedge = (const float*)d_in[15];
    const float* gp_attn  = (const float*)d_in[16];
    const float* gp_bias  = (const float*)d_in[17];
    const float* ln_scale = (const float*)d_in[18];
    const float* ln_bias  = (const float*)d_in[19];
    float* out = (float*)d_out;

    cudaFuncSetAttribute(gemm_mma, cudaFuncAttributeMaxDynamicSharedMemorySize, SMEM_DYN);

    setup<<<(SETUP_TOTAL + 255) / 256, 256>>>(ip_w, gf_wsrc, gf_wdst, gp_wsrc, gp_wdst);  // 1
    count_both<<<(E_FULL + E_PRUNED + 255) / 256, 256>>>(idxF, idxP);                     // 2
    assign_off<<<(N_CELLS + 255) / 256, 256>>>();                                         // 3

    // h = X @ ip_w + ip_b
    gemm_mma<<<dim3(1, (N_CELLS + 127) / 128), 256, SMEM_DYN>>>(
        X, ip_b, /*mode=*/0, N_CELLS, N_GENES, HIDDEN, NC1);                              // 4
    // hcat = g_h @ [wsrcF|wdstF|wsrcP|wdstP]
    gemm_mma<<<dim3(4, (N_CELLS + 127) / 128), 256, SMEM_DYN>>>(
        nullptr, nullptr, /*mode=*/1, N_CELLS, HIDDEN, 512, NC2);                         // 5

    scatter_both<<<(E_FULL + E_PRUNED + 255) / 256, 256>>>(idxF, wF, idxP, wP);           // 6

    gat_finalize<<<(N_CELLS * 32 + 255) / 256, 256>>>(alpha,
                                                      gf_wedge, gf_attn, gf_bias,
                                                      gp_wedge, gp_attn, gp_bias,
                                                      ln_scale, ln_bias, out);            // 7
}